// round 2
// baseline (speedup 1.0000x reference)
#include <cuda_runtime.h>
#include <math.h>

#define DIM        256
#define ROWS       64
#define NTHREADS   256
#define H_PITCH    260   // float4-aligned (1040B), broadcast A-frag reads
#define W_PITCH    68    // 68 mod 32 = 4 -> conflict-free float4 B-frag reads
#define KB         64
#define NLAYERS    6
#define KCHUNKS    (DIM / KB)

// smem layout (floats)
#define OFF_H    0
#define OFF_T    (OFF_H + ROWS * H_PITCH)
#define OFF_W    (OFF_T + ROWS * H_PITCH)
#define OFF_AN   (OFF_W + DIM * W_PITCH)
#define OFF_B1   (OFF_AN + 3 * DIM)
#define OFF_B2   (OFF_B1 + DIM)
#define OFF_RED  (OFF_B2 + DIM)          // 64 rows * 4 parts * 4 vals
#define OFF_CF   (OFF_RED + ROWS * 16)   // 64 rows * 4 coefs
#define SMEM_FLOATS (OFF_CF + ROWS * 4)  // ~53.2K floats = ~208 KB

__device__ __forceinline__ float dot4(float4 a, float4 b) {
    return fmaf(a.x, b.x, fmaf(a.y, b.y, fmaf(a.z, b.z, a.w * b.w)));
}

__global__ __launch_bounds__(NTHREADS, 1)
void collapse_engine_kernel(const float* __restrict__ h0,
                            const float* __restrict__ W1g,
                            const float* __restrict__ b1g,
                            const float* __restrict__ W2g,
                            const float* __restrict__ b2g,
                            const float* __restrict__ anchors,
                            float* __restrict__ out_h,
                            float* __restrict__ out_align,
                            float* __restrict__ out_div,
                            float* __restrict__ out_ten,
                            int B)
{
    extern __shared__ float smem[];
    float* sh_h  = smem + OFF_H;
    float* sh_t  = smem + OFF_T;
    float* sh_W  = smem + OFF_W;
    float* sh_an = smem + OFF_AN;
    float* sh_b1 = smem + OFF_B1;
    float* sh_b2 = smem + OFF_B2;
    float* sh_rd = smem + OFF_RED;
    float* sh_cf = smem + OFF_CF;

    const int t   = threadIdx.x;
    const int tx  = t & 31;   // n-dim lane
    const int ty  = t >> 5;   // m-dim group (warp id)
    const int row0 = blockIdx.x * ROWS;

    // ---- stage h tile + anchors + biases ----
    {
        const float4* g = (const float4*)(h0 + (size_t)row0 * DIM);
        #pragma unroll
        for (int it = 0; it < (ROWS * DIM / 4) / NTHREADS; it++) {
            int q = t + it * NTHREADS;
            int r = q >> 6;            // 64 quads per row
            int c = (q & 63) << 2;
            float4 v = g[(size_t)r * 64 + (q & 63)];
            *(float4*)(sh_h + r * H_PITCH + c) = v;
        }
        for (int i = t; i < 3 * DIM; i += NTHREADS) sh_an[i] = anchors[i];
        for (int i = t; i < DIM; i += NTHREADS) { sh_b1[i] = b1g[i]; sh_b2[i] = b2g[i]; }
    }
    __syncthreads();

    // ---- normalize anchors (3 lanes; once per block, trivial) ----
    if (t < 3) {
        float s = 0.f;
        for (int c = 0; c < DIM; c++) { float v = sh_an[t * DIM + c]; s += v * v; }
        float inv = 1.f / fmaxf(sqrtf(s), 1e-12f);
        for (int c = 0; c < DIM; c++) sh_an[t * DIM + c] *= inv;
    }
    __syncthreads();

    for (int layer = 0; layer < NLAYERS; layer++) {
        // ---------- per-row reductions: h.h, h.a0, h.a1, h.a2 ----------
        {
            int r = t & 63;           // row
            int p = t >> 6;           // 64-float segment
            const float4* hr = (const float4*)(sh_h + r * H_PITCH + p * 64);
            const float4* a0 = (const float4*)(sh_an + p * 64);
            const float4* a1 = (const float4*)(sh_an + DIM + p * 64);
            const float4* a2 = (const float4*)(sh_an + 2 * DIM + p * 64);
            float hh = 0.f, d0 = 0.f, d1 = 0.f, d2 = 0.f;
            #pragma unroll
            for (int q = 0; q < 16; q++) {
                float4 v = hr[q];
                hh += dot4(v, v);
                d0 += dot4(v, a0[q]);
                d1 += dot4(v, a1[q]);
                d2 += dot4(v, a2[q]);
            }
            float* red = sh_rd + (r * 4 + p) * 4;
            red[0] = hh; red[1] = d0; red[2] = d1; red[3] = d2;
        }
        __syncthreads();

        // combine per row; compute traces + force coefficients
        if (t < ROWS) {
            const float* red = sh_rd + t * 16;
            float hh = red[0] + red[4] + red[8]  + red[12];
            float d0 = red[1] + red[5] + red[9]  + red[13];
            float d1 = red[2] + red[6] + red[10] + red[14];
            float d2 = red[3] + red[7] + red[11] + red[15];
            float invn = 1.f / fmaxf(sqrtf(hh), 1e-12f);
            float al0 = d0 * invn, al1 = d1 * invn, al2 = d2 * invn;
            float dv0 = 1.f - al0, dv1 = 1.f - al1, dv2 = 1.f - al2;

            size_t base = ((size_t)layer * B + (row0 + t)) * 3;
            out_align[base + 0] = al0; out_align[base + 1] = al1; out_align[base + 2] = al2;
            out_div[base + 0] = dv0;  out_div[base + 1] = dv1;  out_div[base + 2] = dv2;
            out_ten[base + 0] = fabsf(dv0); out_ten[base + 1] = fabsf(dv1); out_ten[base + 2] = fabsf(dv2);

            // ||h - a||^2 = hh - 2 h.a + 1  (anchors unit)
            float r0 = sqrtf(fmaxf(hh - 2.f * d0 + 1.f, 0.f));
            float r1 = sqrtf(fmaxf(hh - 2.f * d1 + 1.f, 0.f));
            float r2 = sqrtf(fmaxf(hh - 2.f * d2 + 1.f, 0.f));
            float q0 = 0.1f * dv0 / fmaxf(r0, 1e-12f);
            float q1 = 0.1f * dv1 / fmaxf(r1, 1e-12f);
            float q2 = 0.1f * dv2 / fmaxf(r2, 1e-12f);
            float* cf = sh_cf + t * 4;
            cf[0] = 1.f - (q0 + q1 + q2);        // coefficient of h
            cf[1] = q0; cf[2] = q1; cf[3] = q2;  // coefficients of anchors
        }

        // ---------- GEMM1: sh_t = tanh(sh_h @ W1^T + b1) ----------
        {
            float acc[8][8];
            #pragma unroll
            for (int i = 0; i < 8; i++)
                #pragma unroll
                for (int j = 0; j < 8; j++) acc[i][j] = 0.f;

            for (int kc = 0; kc < KCHUNKS; kc++) {
                __syncthreads();
                {   // stage W1[:, kc*64 .. +63] -> sh_W, coalesced
                    #pragma unroll
                    for (int it = 0; it < 16; it++) {
                        int q  = t + it * NTHREADS;     // quad index over 256 rows x 16 quads
                        int r  = q >> 4;                // W row (output n)
                        int qq = q & 15;                // quad within chunk
                        float4 v = *(const float4*)(W1g + (size_t)r * DIM + kc * KB + (qq << 2));
                        *(float4*)(sh_W + r * W_PITCH + (qq << 2)) = v;
                    }
                }
                __syncthreads();
                const float* Ab = sh_h + (ty * 8) * H_PITCH + kc * KB;
                const float* Wb = sh_W + tx * W_PITCH;
                #pragma unroll 2
                for (int kq = 0; kq < KB / 4; kq++) {
                    float4 a4[8], b4[8];
                    #pragma unroll
                    for (int i = 0; i < 8; i++)
                        a4[i] = *(const float4*)(Ab + i * H_PITCH + (kq << 2));
                    #pragma unroll
                    for (int j = 0; j < 8; j++)
                        b4[j] = *(const float4*)(Wb + j * 32 * W_PITCH + (kq << 2));
                    #pragma unroll
                    for (int i = 0; i < 8; i++)
                        #pragma unroll
                        for (int j = 0; j < 8; j++) {
                            acc[i][j] = fmaf(a4[i].x, b4[j].x, acc[i][j]);
                            acc[i][j] = fmaf(a4[i].y, b4[j].y, acc[i][j]);
                            acc[i][j] = fmaf(a4[i].z, b4[j].z, acc[i][j]);
                            acc[i][j] = fmaf(a4[i].w, b4[j].w, acc[i][j]);
                        }
                }
            }
            // epilogue: tanh + b1 -> sh_t
            #pragma unroll
            for (int i = 0; i < 8; i++) {
                int m = ty * 8 + i;
                #pragma unroll
                for (int j = 0; j < 8; j++) {
                    int n = tx + 32 * j;
                    sh_t[m * H_PITCH + n] = tanhf(acc[i][j] + sh_b1[n]);
                }
            }
        }

        // ---------- GEMM2: h_new = cf0*h + (sh_t @ W2^T + b2) + sum g_a * anchor_a ----------
        {
            float acc[8][8];
            #pragma unroll
            for (int i = 0; i < 8; i++)
                #pragma unroll
                for (int j = 0; j < 8; j++) acc[i][j] = 0.f;

            for (int kc = 0; kc < KCHUNKS; kc++) {
                __syncthreads();   // also orders epilogue1 sh_t writes before reads
                {
                    #pragma unroll
                    for (int it = 0; it < 16; it++) {
                        int q  = t + it * NTHREADS;
                        int r  = q >> 4;
                        int qq = q & 15;
                        float4 v = *(const float4*)(W2g + (size_t)r * DIM + kc * KB + (qq << 2));
                        *(float4*)(sh_W + r * W_PITCH + (qq << 2)) = v;
                    }
                }
                __syncthreads();
                const float* Ab = sh_t + (ty * 8) * H_PITCH + kc * KB;
                const float* Wb = sh_W + tx * W_PITCH;
                #pragma unroll 2
                for (int kq = 0; kq < KB / 4; kq++) {
                    float4 a4[8], b4[8];
                    #pragma unroll
                    for (int i = 0; i < 8; i++)
                        a4[i] = *(const float4*)(Ab + i * H_PITCH + (kq << 2));
                    #pragma unroll
                    for (int j = 0; j < 8; j++)
                        b4[j] = *(const float4*)(Wb + j * 32 * W_PITCH + (kq << 2));
                    #pragma unroll
                    for (int i = 0; i < 8; i++)
                        #pragma unroll
                        for (int j = 0; j < 8; j++) {
                            acc[i][j] = fmaf(a4[i].x, b4[j].x, acc[i][j]);
                            acc[i][j] = fmaf(a4[i].y, b4[j].y, acc[i][j]);
                            acc[i][j] = fmaf(a4[i].z, b4[j].z, acc[i][j]);
                            acc[i][j] = fmaf(a4[i].w, b4[j].w, acc[i][j]);
                        }
                }
            }
            __syncthreads();   // all FMA reads of sh_t done; sh_cf visible
            // epilogue: fused update, in-place into sh_h (each element owned by one thread)
            #pragma unroll
            for (int i = 0; i < 8; i++) {
                int m = ty * 8 + i;
                const float* cf = sh_cf + m * 4;
                float c0 = cf[0], g0 = cf[1], g1 = cf[2], g2 = cf[3];
                #pragma unroll
                for (int j = 0; j < 8; j++) {
                    int n = tx + 32 * j;
                    float hv = sh_h[m * H_PITCH + n];
                    float v = acc[i][j] + sh_b2[n];
                    v = fmaf(c0, hv, v);
                    v = fmaf(g0, sh_an[n], v);
                    v = fmaf(g1, sh_an[DIM + n], v);
                    v = fmaf(g2, sh_an[2 * DIM + n], v);
                    sh_h[m * H_PITCH + n] = v;
                }
            }
        }
        __syncthreads();

        // ---------- norm clip ----------
        {
            int r = t & 63;
            int p = t >> 6;
            const float4* hr = (const float4*)(sh_h + r * H_PITCH + p * 64);
            float hh = 0.f;
            #pragma unroll
            for (int q = 0; q < 16; q++) { float4 v = hr[q]; hh += dot4(v, v); }
            sh_rd[r * 4 + p] = hh;
        }
        __syncthreads();
        if (t < ROWS) {
            float hh = sh_rd[t * 4] + sh_rd[t * 4 + 1] + sh_rd[t * 4 + 2] + sh_rd[t * 4 + 3];
            float n = sqrtf(hh);
            sh_cf[t] = (n > 10.0f) ? (10.0f / (n + 1e-8f)) : 1.0f;  // cf reuse safe past epilogue2
        }
        __syncthreads();
        {   // scale rows (unconditional multiply; s==1 when not clipped)
            #pragma unroll
            for (int it = 0; it < (ROWS * 64) / NTHREADS; it++) {
                int q = t + it * NTHREADS;
                int r = q >> 6;
                int c = (q & 63) << 2;
                float s = sh_cf[r];
                float4* p4 = (float4*)(sh_h + r * H_PITCH + c);
                float4 v = *p4;
                v.x *= s; v.y *= s; v.z *= s; v.w *= s;
                *p4 = v;
            }
        }
        __syncthreads();
    }

    // ---- write h_final ----
    {
        float4* g = (float4*)(out_h + (size_t)row0 * DIM);
        #pragma unroll
        for (int it = 0; it < (ROWS * DIM / 4) / NTHREADS; it++) {
            int q = t + it * NTHREADS;
            int r = q >> 6;
            int qq = q & 63;
            g[(size_t)r * 64 + qq] = *(float4*)(sh_h + r * H_PITCH + (qq << 2));
        }
    }
}

extern "C" void kernel_launch(void* const* d_in, const int* in_sizes, int n_in,
                              void* d_out, int out_size)
{
    const float* h0      = (const float*)d_in[0];
    const float* W1      = (const float*)d_in[1];
    const float* b1      = (const float*)d_in[2];
    const float* W2      = (const float*)d_in[3];
    const float* b2      = (const float*)d_in[4];
    const float* anchors = (const float*)d_in[5];

    const int B = in_sizes[0] / DIM;

    float* out       = (float*)d_out;
    float* out_h     = out;                                  // [B, 256]
    float* out_align = out_h + (size_t)B * DIM;              // [6, B, 3]
    float* out_div   = out_align + (size_t)NLAYERS * B * 3;  // [6, B, 3]
    float* out_ten   = out_div + (size_t)NLAYERS * B * 3;    // [6, B, 3]

    const size_t smem_bytes = (size_t)SMEM_FLOATS * sizeof(float);  // ~208 KB
    cudaFuncSetAttribute(collapse_engine_kernel,
                         cudaFuncAttributeMaxDynamicSharedMemorySize,
                         (int)smem_bytes);

    collapse_engine_kernel<<<B / ROWS, NTHREADS, smem_bytes>>>(
        h0, W1, b1, W2, b2, anchors,
        out_h, out_align, out_div, out_ten, B);
}